// round 3
// baseline (speedup 1.0000x reference)
#include <cuda_runtime.h>
#include <cstdint>

#define N_NODES 100000
#define N_EDGES 1600000
#define F 256          // IN_FEATS == H_FEATS
#define C 64           // NUM_CLASSES

// ---------------- scratch (static device globals; no allocation) -------------
__device__ int   g_deg_out[N_NODES];
__device__ int   g_deg_in[N_NODES];
__device__ float g_h[(size_t)N_NODES * F];    // (x * rsqrt(deg_out)) @ W
__device__ float g_agg[(size_t)N_NODES * F];  // scatter-add target
__device__ float g_pooled[F];                 // sum over nodes of relu(...)
__device__ int   g_is64;                      // 1 if src/dst are int64, 0 if int32

// ---------------- K-1: index dtype probe --------------------------------------
// int64 indices in [0, N_NODES) have high word == 0 for every element.
// int32 indices make the "high words" random node ids (~all nonzero).
__global__ void detect_kernel(const unsigned int* __restrict__ words) {
    __shared__ int nonzero;
    if (threadIdx.x == 0) nonzero = 0;
    __syncthreads();
    // inspect 1024 (lo,hi) pairs = 2048 words; valid under both interpretations
    for (int p = threadIdx.x; p < 1024; p += blockDim.x) {
        if (words[2 * p + 1] != 0u) atomicOr(&nonzero, 1);
    }
    __syncthreads();
    if (threadIdx.x == 0) g_is64 = (nonzero == 0) ? 1 : 0;
}

__device__ __forceinline__ int load_idx(const void* p, int i, int is64) {
    return is64 ? (int)((const long long*)p)[i] : ((const int*)p)[i];
}

// ---------------- K0: zero scratch -------------------------------------------
__global__ void zero_kernel(int nodes) {
    size_t tid    = (size_t)blockIdx.x * blockDim.x + threadIdx.x;
    size_t stride = (size_t)gridDim.x * blockDim.x;
    size_t total4 = (size_t)nodes * F / 4;
    float4 z = make_float4(0.f, 0.f, 0.f, 0.f);
    float4* agg4 = reinterpret_cast<float4*>(g_agg);
    for (size_t i = tid; i < total4; i += stride) agg4[i] = z;
    for (size_t i = tid; i < (size_t)nodes; i += stride) {
        g_deg_out[i] = 0;
        g_deg_in[i]  = 0;
    }
    if (tid < F) g_pooled[tid] = 0.f;
}

// ---------------- K1: degree counts ------------------------------------------
__global__ void deg_kernel(const void* __restrict__ src,
                           const void* __restrict__ dst, int nE) {
    int i = blockIdx.x * blockDim.x + threadIdx.x;
    int is64 = g_is64;
    if (i < nE) {
        atomicAdd(&g_deg_out[load_idx(src, i, is64)], 1);
        atomicAdd(&g_deg_in[load_idx(dst, i, is64)], 1);
    }
}

// ---------------- K2: GEMM  h = (x * rsqrt(deg_out)) @ W ---------------------
// 64x64 tile, BK=16, 256 threads, 4x4 register micro-tiles. Row scale fused at
// the output (scale distributes over the K-sum).
#define BM 64
#define BN 64
#define BK 16

__global__ __launch_bounds__(256) void gemm_kernel(const float* __restrict__ x,
                                                   const float* __restrict__ W,
                                                   int M) {
    __shared__ float As[BK][BM + 4];   // transposed A tile (row stride 272B, 16B-aligned)
    __shared__ float Bs[BK][BN];

    const int t  = threadIdx.x;
    const int bm = blockIdx.x * BM;
    const int bn = blockIdx.y * BN;
    const int tx = t & 15;
    const int ty = t >> 4;

    const int aRow  = t >> 2;          // 0..63
    const int aCol4 = (t & 3) << 2;    // 0,4,8,12
    const int bRow  = t >> 4;          // 0..15
    const int bCol4 = (t & 15) << 2;   // 0..60

    float acc[4][4] = {};

    for (int k0 = 0; k0 < F; k0 += BK) {
        float4 av = make_float4(0.f, 0.f, 0.f, 0.f);
        if (bm + aRow < M)
            av = *reinterpret_cast<const float4*>(x + (size_t)(bm + aRow) * F + k0 + aCol4);
        As[aCol4 + 0][aRow] = av.x;
        As[aCol4 + 1][aRow] = av.y;
        As[aCol4 + 2][aRow] = av.z;
        As[aCol4 + 3][aRow] = av.w;

        float4 bv = *reinterpret_cast<const float4*>(W + (size_t)(k0 + bRow) * F + bn + bCol4);
        *reinterpret_cast<float4*>(&Bs[bRow][bCol4]) = bv;

        __syncthreads();

#pragma unroll
        for (int k = 0; k < BK; k++) {
            float4 ra = *reinterpret_cast<const float4*>(&As[k][ty << 2]);
            float4 rb = *reinterpret_cast<const float4*>(&Bs[k][tx << 2]);
            float a[4] = {ra.x, ra.y, ra.z, ra.w};
            float b[4] = {rb.x, rb.y, rb.z, rb.w};
#pragma unroll
            for (int i = 0; i < 4; i++)
#pragma unroll
                for (int j = 0; j < 4; j++) acc[i][j] = fmaf(a[i], b[j], acc[i][j]);
        }
        __syncthreads();
    }

#pragma unroll
    for (int i = 0; i < 4; i++) {
        int m = bm + (ty << 2) + i;
        if (m < M) {
            float s = rsqrtf((float)max(g_deg_out[m], 1));
            float4 o = make_float4(acc[i][0] * s, acc[i][1] * s, acc[i][2] * s, acc[i][3] * s);
            *reinterpret_cast<float4*>(g_h + (size_t)m * F + bn + (tx << 2)) = o;
        }
    }
}

// ---------------- K3: edge scatter  agg[dst] += h[src] -----------------------
// One warp per edge. Lane l handles float4 chunks l and l+32 of the 256-float row.
__global__ __launch_bounds__(256) void edge_kernel(const void* __restrict__ src,
                                                   const void* __restrict__ dst,
                                                   int nE) {
    int warp = (blockIdx.x * blockDim.x + threadIdx.x) >> 5;
    int lane = threadIdx.x & 31;
    if (warp >= nE) return;
    int is64 = g_is64;
    int s = load_idx(src, warp, is64);
    int d = load_idx(dst, warp, is64);
    const float4* hrow = reinterpret_cast<const float4*>(g_h + (size_t)s * F);
    float* arow = g_agg + (size_t)d * F;
#pragma unroll
    for (int i = 0; i < 2; i++) {
        int c4 = lane + i * 32;           // float4 index 0..63
        float4 v = hrow[c4];
        int base = c4 << 2;
        atomicAdd(arow + base + 0, v.x);
        atomicAdd(arow + base + 1, v.y);
        atomicAdd(arow + base + 2, v.z);
        atomicAdd(arow + base + 3, v.w);
    }
}

// ---------------- K4: epilogue + mean pool ------------------------------------
// pooled[f] += sum_{rows in block} relu(agg[n][f] * rsqrt(deg_in[n]) + b[f])
#define ROWS_PER_BLOCK 128
__global__ __launch_bounds__(256) void pool_kernel(const float* __restrict__ b, int nodes) {
    int f = threadIdx.x;                       // 0..255
    float bj  = b[f];
    float acc = 0.f;
    int r0 = blockIdx.x * ROWS_PER_BLOCK;
    int r1 = min(r0 + ROWS_PER_BLOCK, nodes);
    for (int r = r0; r < r1; r++) {
        float rs = rsqrtf((float)max(g_deg_in[r], 1));
        float v  = fmaf(g_agg[(size_t)r * F + f], rs, bj);
        acc += fmaxf(v, 0.f);
    }
    atomicAdd(&g_pooled[f], acc);
}

// ---------------- K5: head  softmax(pooled/N @ W2 + b2) ----------------------
__global__ __launch_bounds__(64) void head_kernel(const float* __restrict__ W2,
                                                  const float* __restrict__ b2,
                                                  float* __restrict__ out, float invN) {
    __shared__ float pooled_s[F];
    __shared__ float sm[C];
    int t = threadIdx.x;   // 64 threads
    for (int j = t; j < F; j += C) pooled_s[j] = g_pooled[j] * invN;
    __syncthreads();

    float acc = b2[t];
#pragma unroll 8
    for (int j = 0; j < F; j++) acc = fmaf(pooled_s[j], W2[(size_t)j * C + t], acc);

    sm[t] = acc;
    __syncthreads();
    float m = sm[0];
#pragma unroll
    for (int j = 1; j < C; j++) m = fmaxf(m, sm[j]);
    __syncthreads();
    float e = expf(acc - m);
    sm[t] = e;
    __syncthreads();
    float ssum = 0.f;
#pragma unroll
    for (int j = 0; j < C; j++) ssum += sm[j];
    out[t] = e / ssum;
}

// ---------------- launch ------------------------------------------------------
extern "C" void kernel_launch(void* const* d_in, const int* in_sizes, int n_in,
                              void* d_out, int out_size) {
    const float* x   = (const float*)d_in[0];
    const void*  src = d_in[1];
    const void*  dst = d_in[2];
    const float* W   = (const float*)d_in[3];
    const float* b   = (const float*)d_in[4];
    const float* W2  = (const float*)d_in[5];
    const float* b2  = (const float*)d_in[6];
    float*       out = (float*)d_out;

    const int nodes = in_sizes[0] / F;     // 100000
    const int nE    = in_sizes[1];         // 1600000

    // K-1: probe index dtype (int32 vs int64)
    detect_kernel<<<1, 256>>>((const unsigned int*)src);

    // K0: zero scratch
    zero_kernel<<<1024, 256>>>(nodes);

    // K1: degrees
    deg_kernel<<<(nE + 255) / 256, 256>>>(src, dst, nE);

    // K2: GEMM (fused rsqrt(out_deg) row scale)
    dim3 ggrid((nodes + BM - 1) / BM, F / BN);
    gemm_kernel<<<ggrid, 256>>>(x, W, nodes);

    // K3: edge scatter-add (warp per edge)
    long long ethreads = (long long)nE * 32;
    int eblocks = (int)((ethreads + 255) / 256);
    edge_kernel<<<eblocks, 256>>>(src, dst, nE);

    // K4: relu + mean pool (sum)
    pool_kernel<<<(nodes + ROWS_PER_BLOCK - 1) / ROWS_PER_BLOCK, 256>>>(b, nodes);

    // K5: head + softmax
    head_kernel<<<1, C>>>(W2, b2, out, 1.0f / (float)nodes);
}

// round 4
// speedup vs baseline: 1.8110x; 1.8110x over previous
#include <cuda_runtime.h>
#include <cstdint>

#define N_NODES 100000
#define N_EDGES 1600000
#define F 256          // IN_FEATS == H_FEATS
#define C 64           // NUM_CLASSES

// ---------------- scratch (static device globals; no allocation) -------------
__device__ int   g_deg_out[N_NODES];
__device__ int   g_deg_in[N_NODES];
__device__ float g_h[(size_t)N_NODES * F];    // (x * rsqrt(deg_out)) @ W
__device__ float g_agg[(size_t)N_NODES * F];  // scatter-add target
__device__ float g_pooled[F];                 // sum over nodes of relu(...)
__device__ int   g_is64;                      // 1 if src/dst are int64, 0 if int32

// ---------------- K-1: index dtype probe --------------------------------------
__global__ void detect_kernel(const unsigned int* __restrict__ words) {
    __shared__ int nonzero;
    if (threadIdx.x == 0) nonzero = 0;
    __syncthreads();
    for (int p = threadIdx.x; p < 1024; p += blockDim.x) {
        if (words[2 * p + 1] != 0u) atomicOr(&nonzero, 1);
    }
    __syncthreads();
    if (threadIdx.x == 0) g_is64 = (nonzero == 0) ? 1 : 0;
}

__device__ __forceinline__ int load_idx(const void* p, int i, int is64) {
    return is64 ? (int)((const long long*)p)[i] : ((const int*)p)[i];
}

// ---------------- K0: zero scratch -------------------------------------------
__global__ void zero_kernel(int nodes) {
    size_t tid    = (size_t)blockIdx.x * blockDim.x + threadIdx.x;
    size_t stride = (size_t)gridDim.x * blockDim.x;
    size_t total4 = (size_t)nodes * F / 4;
    float4 z = make_float4(0.f, 0.f, 0.f, 0.f);
    float4* agg4 = reinterpret_cast<float4*>(g_agg);
    for (size_t i = tid; i < total4; i += stride) agg4[i] = z;
    for (size_t i = tid; i < (size_t)nodes; i += stride) {
        g_deg_out[i] = 0;
        g_deg_in[i]  = 0;
    }
    if (tid < F) g_pooled[tid] = 0.f;
}

// ---------------- K1: degree counts ------------------------------------------
__global__ void deg_kernel(const void* __restrict__ src,
                           const void* __restrict__ dst, int nE) {
    int i = blockIdx.x * blockDim.x + threadIdx.x;
    int is64 = g_is64;
    if (i < nE) {
        atomicAdd(&g_deg_out[load_idx(src, i, is64)], 1);
        atomicAdd(&g_deg_in[load_idx(dst, i, is64)], 1);
    }
}

// ---------------- K2: GEMM  h = (x * rsqrt(deg_out)) @ W ---------------------
// 128x64 block tile, BK=16, 256 threads, 8x4 register micro-tiles.
// Row scale rsqrt(deg_out) fused at output.
#define BM 128
#define BN 64
#define BK 16

__global__ __launch_bounds__(256) void gemm_kernel(const float* __restrict__ x,
                                                   const float* __restrict__ W,
                                                   int M) {
    __shared__ float As[BK][BM + 4];   // transposed A tile (16B-aligned rows)
    __shared__ float Bs[BK][BN];

    const int t  = threadIdx.x;
    const int bm = blockIdx.x * BM;
    const int bn = blockIdx.y * BN;
    const int tx = t & 15;             // 0..15 -> col group of 4
    const int ty = t >> 4;             // 0..15 -> row group of 8

    // A tile: 128 rows x 16 cols = 512 float4 -> 2 per thread
    const int aRow  = t >> 2;          // 0..63 (and +64)
    const int aCol4 = (t & 3) << 2;    // 0,4,8,12
    // B tile: 16 rows x 64 cols = 256 float4 -> 1 per thread
    const int bRow  = t >> 4;          // 0..15
    const int bCol4 = (t & 15) << 2;   // 0..60

    float acc[8][4] = {};

    for (int k0 = 0; k0 < F; k0 += BK) {
#pragma unroll
        for (int half = 0; half < 2; half++) {
            int r = aRow + half * 64;
            float4 av = make_float4(0.f, 0.f, 0.f, 0.f);
            if (bm + r < M)
                av = *reinterpret_cast<const float4*>(x + (size_t)(bm + r) * F + k0 + aCol4);
            As[aCol4 + 0][r] = av.x;
            As[aCol4 + 1][r] = av.y;
            As[aCol4 + 2][r] = av.z;
            As[aCol4 + 3][r] = av.w;
        }
        float4 bv = *reinterpret_cast<const float4*>(W + (size_t)(k0 + bRow) * F + bn + bCol4);
        *reinterpret_cast<float4*>(&Bs[bRow][bCol4]) = bv;

        __syncthreads();

#pragma unroll
        for (int k = 0; k < BK; k++) {
            float4 ra0 = *reinterpret_cast<const float4*>(&As[k][ty << 3]);
            float4 ra1 = *reinterpret_cast<const float4*>(&As[k][(ty << 3) + 4]);
            float4 rb  = *reinterpret_cast<const float4*>(&Bs[k][tx << 2]);
            float a[8] = {ra0.x, ra0.y, ra0.z, ra0.w, ra1.x, ra1.y, ra1.z, ra1.w};
            float b[4] = {rb.x, rb.y, rb.z, rb.w};
#pragma unroll
            for (int i = 0; i < 8; i++)
#pragma unroll
                for (int j = 0; j < 4; j++) acc[i][j] = fmaf(a[i], b[j], acc[i][j]);
        }
        __syncthreads();
    }

#pragma unroll
    for (int i = 0; i < 8; i++) {
        int m = bm + (ty << 3) + i;
        if (m < M) {
            float s = rsqrtf((float)max(g_deg_out[m], 1));
            float4 o = make_float4(acc[i][0] * s, acc[i][1] * s, acc[i][2] * s, acc[i][3] * s);
            *reinterpret_cast<float4*>(g_h + (size_t)m * F + bn + (tx << 2)) = o;
        }
    }
}

// ---------------- K3: edge scatter  agg[dst] += h[src] -----------------------
// One warp per edge. Vector reductions: red.global.add.v4.f32 (16B, no return).
__device__ __forceinline__ void red_add_v4(float* addr, float4 v) {
    asm volatile("red.global.add.v4.f32 [%0], {%1, %2, %3, %4};"
                 :: "l"(addr), "f"(v.x), "f"(v.y), "f"(v.z), "f"(v.w)
                 : "memory");
}

__global__ __launch_bounds__(256) void edge_kernel(const void* __restrict__ src,
                                                   const void* __restrict__ dst,
                                                   int nE) {
    int warp = (blockIdx.x * blockDim.x + threadIdx.x) >> 5;
    int lane = threadIdx.x & 31;
    if (warp >= nE) return;
    int is64 = g_is64;
    int s = load_idx(src, warp, is64);
    int d = load_idx(dst, warp, is64);
    const float4* hrow = reinterpret_cast<const float4*>(g_h + (size_t)s * F);
    float* arow = g_agg + (size_t)d * F;

    float4 v0 = hrow[lane];
    float4 v1 = hrow[lane + 32];
    red_add_v4(arow + (lane << 2), v0);
    red_add_v4(arow + ((lane + 32) << 2), v1);
}

// ---------------- K4: epilogue + mean pool ------------------------------------
#define ROWS_PER_BLOCK 128
__global__ __launch_bounds__(256) void pool_kernel(const float* __restrict__ b, int nodes) {
    int f = threadIdx.x;                       // 0..255
    float bj  = b[f];
    float acc = 0.f;
    int r0 = blockIdx.x * ROWS_PER_BLOCK;
    int r1 = min(r0 + ROWS_PER_BLOCK, nodes);
    for (int r = r0; r < r1; r++) {
        float rs = rsqrtf((float)max(g_deg_in[r], 1));
        float v  = fmaf(g_agg[(size_t)r * F + f], rs, bj);
        acc += fmaxf(v, 0.f);
    }
    atomicAdd(&g_pooled[f], acc);
}

// ---------------- K5: head  softmax(pooled/N @ W2 + b2) ----------------------
__global__ __launch_bounds__(64) void head_kernel(const float* __restrict__ W2,
                                                  const float* __restrict__ b2,
                                                  float* __restrict__ out, float invN) {
    __shared__ float pooled_s[F];
    __shared__ float sm[C];
    int t = threadIdx.x;   // 64 threads
    for (int j = t; j < F; j += C) pooled_s[j] = g_pooled[j] * invN;
    __syncthreads();

    float acc = b2[t];
#pragma unroll 8
    for (int j = 0; j < F; j++) acc = fmaf(pooled_s[j], W2[(size_t)j * C + t], acc);

    sm[t] = acc;
    __syncthreads();
    float m = sm[0];
#pragma unroll
    for (int j = 1; j < C; j++) m = fmaxf(m, sm[j]);
    __syncthreads();
    float e = expf(acc - m);
    sm[t] = e;
    __syncthreads();
    float ssum = 0.f;
#pragma unroll
    for (int j = 0; j < C; j++) ssum += sm[j];
    out[t] = e / ssum;
}

// ---------------- launch ------------------------------------------------------
extern "C" void kernel_launch(void* const* d_in, const int* in_sizes, int n_in,
                              void* d_out, int out_size) {
    const float* x   = (const float*)d_in[0];
    const void*  src = d_in[1];
    const void*  dst = d_in[2];
    const float* W   = (const float*)d_in[3];
    const float* b   = (const float*)d_in[4];
    const float* W2  = (const float*)d_in[5];
    const float* b2  = (const float*)d_in[6];
    float*       out = (float*)d_out;

    const int nodes = in_sizes[0] / F;     // 100000
    const int nE    = in_sizes[1];         // 1600000

    // K-1: probe index dtype (int32 vs int64)
    detect_kernel<<<1, 256>>>((const unsigned int*)src);

    // K0: zero scratch
    zero_kernel<<<1024, 256>>>(nodes);

    // K1: degrees
    deg_kernel<<<(nE + 255) / 256, 256>>>(src, dst, nE);

    // K2: GEMM (fused rsqrt(out_deg) row scale)
    dim3 ggrid((nodes + BM - 1) / BM, F / BN);
    gemm_kernel<<<ggrid, 256>>>(x, W, nodes);

    // K3: edge scatter-add (warp per edge, v4 reductions)
    long long ethreads = (long long)nE * 32;
    int eblocks = (int)((ethreads + 255) / 256);
    edge_kernel<<<eblocks, 256>>>(src, dst, nE);

    // K4: relu + mean pool (sum)
    pool_kernel<<<(nodes + ROWS_PER_BLOCK - 1) / ROWS_PER_BLOCK, 256>>>(b, nodes);

    // K5: head + softmax
    head_kernel<<<1, C>>>(W2, b2, out, 1.0f / (float)nodes);
}

// round 5
// speedup vs baseline: 2.8707x; 1.5851x over previous
#include <cuda_runtime.h>
#include <cstdint>

#define N_NODES 100000
#define N_EDGES 1600000
#define F 256          // IN_FEATS == H_FEATS
#define C 64           // NUM_CLASSES

// ---------------- scratch (static device globals; no allocation) -------------
__device__ int   g_deg_out[N_NODES];
__device__ int   g_deg_in[N_NODES];
__device__ float g_h[(size_t)N_NODES * F];      // (x * rsqrt(deg_out)) @ W
__device__ float g_pooled[F];                   // sum over nodes of relu(...)
__device__ int   g_is64;                        // 1 if src/dst are int64
// CSR-by-dst
__device__ int   g_row_ptr[N_NODES + 1];
__device__ int   g_cursor[N_NODES];
__device__ int   g_edge_src[N_EDGES];
#define SCAN_BLOCKS 1024                        // covers up to 262144 nodes @256/blk
__device__ int   g_blocksum[SCAN_BLOCKS];
__device__ int   g_blockoff[SCAN_BLOCKS];

// ---------------- K-1: index dtype probe --------------------------------------
__global__ void detect_kernel(const unsigned int* __restrict__ words) {
    __shared__ int nonzero;
    if (threadIdx.x == 0) nonzero = 0;
    __syncthreads();
    for (int p = threadIdx.x; p < 1024; p += blockDim.x)
        if (words[2 * p + 1] != 0u) atomicOr(&nonzero, 1);
    __syncthreads();
    if (threadIdx.x == 0) g_is64 = (nonzero == 0) ? 1 : 0;
}

__device__ __forceinline__ int load_idx(const void* p, int i, int is64) {
    return is64 ? (int)((const long long*)p)[i] : ((const int*)p)[i];
}

// ---------------- K0: zero scratch -------------------------------------------
__global__ void zero_kernel(int nodes) {
    int tid    = blockIdx.x * blockDim.x + threadIdx.x;
    int stride = gridDim.x * blockDim.x;
    for (int i = tid; i < nodes; i += stride) {
        g_deg_out[i] = 0;
        g_deg_in[i]  = 0;
    }
    if (tid < F) g_pooled[tid] = 0.f;
}

// ---------------- K1: degree counts ------------------------------------------
__global__ void deg_kernel(const void* __restrict__ src,
                           const void* __restrict__ dst, int nE) {
    int i = blockIdx.x * blockDim.x + threadIdx.x;
    int is64 = g_is64;
    if (i < nE) {
        atomicAdd(&g_deg_out[load_idx(src, i, is64)], 1);
        atomicAdd(&g_deg_in[load_idx(dst, i, is64)], 1);
    }
}

// ---------------- CSR build: 3-phase block scan of deg_in --------------------
// Phase A: per-block sums (256 elements per block)
__global__ void scan_a_kernel(int nodes) {
    __shared__ int s[256];
    int i = blockIdx.x * 256 + threadIdx.x;
    s[threadIdx.x] = (i < nodes) ? g_deg_in[i] : 0;
    __syncthreads();
#pragma unroll
    for (int off = 128; off > 0; off >>= 1) {
        if (threadIdx.x < off) s[threadIdx.x] += s[threadIdx.x + off];
        __syncthreads();
    }
    if (threadIdx.x == 0) g_blocksum[blockIdx.x] = s[0];
}

// Phase B: exclusive scan of block sums (single block, Hillis-Steele)
__global__ void scan_b_kernel(int nblocks) {
    __shared__ int s[SCAN_BLOCKS];
    int t = threadIdx.x;                     // 1024 threads
    s[t] = (t < nblocks) ? g_blocksum[t] : 0;
    __syncthreads();
#pragma unroll
    for (int off = 1; off < SCAN_BLOCKS; off <<= 1) {
        int v = (t >= off) ? s[t - off] : 0;
        __syncthreads();
        s[t] += v;
        __syncthreads();
    }
    if (t < nblocks) g_blockoff[t] = (t == 0) ? 0 : s[t - 1];
}

// Phase C: per-block exclusive scan + offset -> row_ptr, init cursor
__global__ void scan_c_kernel(int nodes) {
    __shared__ int s[256];
    int i = blockIdx.x * 256 + threadIdx.x;
    int t = threadIdx.x;
    int d = (i < nodes) ? g_deg_in[i] : 0;
    s[t] = d;
    __syncthreads();
#pragma unroll
    for (int off = 1; off < 256; off <<= 1) {
        int v = (t >= off) ? s[t - off] : 0;
        __syncthreads();
        s[t] += v;
        __syncthreads();
    }
    int excl = g_blockoff[blockIdx.x] + s[t] - d;   // exclusive prefix
    if (i < nodes) {
        g_row_ptr[i] = excl;
        g_cursor[i]  = excl;
        if (i == nodes - 1) g_row_ptr[nodes] = excl + d;
    }
}

// scatter edges into CSR
__global__ void scatter_kernel(const void* __restrict__ src,
                               const void* __restrict__ dst, int nE) {
    int i = blockIdx.x * blockDim.x + threadIdx.x;
    int is64 = g_is64;
    if (i < nE) {
        int d = load_idx(dst, i, is64);
        int pos = atomicAdd(&g_cursor[d], 1);
        g_edge_src[pos] = load_idx(src, i, is64);
    }
}

// ---------------- K2: GEMM  h = (x * rsqrt(deg_out)) @ W ---------------------
#define BM 128
#define BN 64
#define BK 16

__global__ __launch_bounds__(256) void gemm_kernel(const float* __restrict__ x,
                                                   const float* __restrict__ W,
                                                   int M) {
    __shared__ float As[BK][BM + 4];
    __shared__ float Bs[BK][BN];

    const int t  = threadIdx.x;
    const int bm = blockIdx.x * BM;
    const int bn = blockIdx.y * BN;
    const int tx = t & 15;
    const int ty = t >> 4;

    const int aRow  = t >> 2;
    const int aCol4 = (t & 3) << 2;
    const int bRow  = t >> 4;
    const int bCol4 = (t & 15) << 2;

    float acc[8][4] = {};

    for (int k0 = 0; k0 < F; k0 += BK) {
#pragma unroll
        for (int half = 0; half < 2; half++) {
            int r = aRow + half * 64;
            float4 av = make_float4(0.f, 0.f, 0.f, 0.f);
            if (bm + r < M)
                av = *reinterpret_cast<const float4*>(x + (size_t)(bm + r) * F + k0 + aCol4);
            As[aCol4 + 0][r] = av.x;
            As[aCol4 + 1][r] = av.y;
            As[aCol4 + 2][r] = av.z;
            As[aCol4 + 3][r] = av.w;
        }
        float4 bv = *reinterpret_cast<const float4*>(W + (size_t)(k0 + bRow) * F + bn + bCol4);
        *reinterpret_cast<float4*>(&Bs[bRow][bCol4]) = bv;

        __syncthreads();

#pragma unroll
        for (int k = 0; k < BK; k++) {
            float4 ra0 = *reinterpret_cast<const float4*>(&As[k][ty << 3]);
            float4 ra1 = *reinterpret_cast<const float4*>(&As[k][(ty << 3) + 4]);
            float4 rb  = *reinterpret_cast<const float4*>(&Bs[k][tx << 2]);
            float a[8] = {ra0.x, ra0.y, ra0.z, ra0.w, ra1.x, ra1.y, ra1.z, ra1.w};
            float b[4] = {rb.x, rb.y, rb.z, rb.w};
#pragma unroll
            for (int i = 0; i < 8; i++)
#pragma unroll
                for (int j = 0; j < 4; j++) acc[i][j] = fmaf(a[i], b[j], acc[i][j]);
        }
        __syncthreads();
    }

#pragma unroll
    for (int i = 0; i < 8; i++) {
        int m = bm + (ty << 3) + i;
        if (m < M) {
            float s = rsqrtf((float)max(g_deg_out[m], 1));
            float4 o = make_float4(acc[i][0] * s, acc[i][1] * s, acc[i][2] * s, acc[i][3] * s);
            *reinterpret_cast<float4*>(g_h + (size_t)m * F + bn + (tx << 2)) = o;
        }
    }
}

// ---------------- K3: CSR aggregate + epilogue + pool -------------------------
// One warp per dst node. Lane l accumulates float4 chunks l and l+32 of the row.
// Fused: agg*rsqrt(in_deg)+b -> relu -> pooled sum (smem staged, one red/block).
__global__ __launch_bounds__(256) void agg_kernel(const float* __restrict__ b,
                                                  int nodes) {
    __shared__ float pooled_s[F];
    if (threadIdx.x < F) pooled_s[threadIdx.x] = 0.f;
    __syncthreads();

    int warp = (blockIdx.x * blockDim.x + threadIdx.x) >> 5;
    int lane = threadIdx.x & 31;

    if (warp < nodes) {
        int begin = g_row_ptr[warp];
        int end   = g_row_ptr[warp + 1];

        float4 a0 = make_float4(0.f, 0.f, 0.f, 0.f);
        float4 a1 = make_float4(0.f, 0.f, 0.f, 0.f);

        int e = begin;
        // two-edge software pipeline for MLP
        for (; e + 1 < end; e += 2) {
            int s0 = g_edge_src[e];
            int s1 = g_edge_src[e + 1];
            const float4* r0 = reinterpret_cast<const float4*>(g_h + (size_t)s0 * F);
            const float4* r1 = reinterpret_cast<const float4*>(g_h + (size_t)s1 * F);
            float4 v00 = r0[lane], v01 = r0[lane + 32];
            float4 v10 = r1[lane], v11 = r1[lane + 32];
            a0.x += v00.x + v10.x; a0.y += v00.y + v10.y;
            a0.z += v00.z + v10.z; a0.w += v00.w + v10.w;
            a1.x += v01.x + v11.x; a1.y += v01.y + v11.y;
            a1.z += v01.z + v11.z; a1.w += v01.w + v11.w;
        }
        if (e < end) {
            int s0 = g_edge_src[e];
            const float4* r0 = reinterpret_cast<const float4*>(g_h + (size_t)s0 * F);
            float4 v00 = r0[lane], v01 = r0[lane + 32];
            a0.x += v00.x; a0.y += v00.y; a0.z += v00.z; a0.w += v00.w;
            a1.x += v01.x; a1.y += v01.y; a1.z += v01.z; a1.w += v01.w;
        }

        float rs = rsqrtf((float)max(end - begin, 1));
        const float4* b4 = reinterpret_cast<const float4*>(b);
        float4 b0 = b4[lane], b1 = b4[lane + 32];

        float4 o0, o1;
        o0.x = fmaxf(fmaf(a0.x, rs, b0.x), 0.f);
        o0.y = fmaxf(fmaf(a0.y, rs, b0.y), 0.f);
        o0.z = fmaxf(fmaf(a0.z, rs, b0.z), 0.f);
        o0.w = fmaxf(fmaf(a0.w, rs, b0.w), 0.f);
        o1.x = fmaxf(fmaf(a1.x, rs, b1.x), 0.f);
        o1.y = fmaxf(fmaf(a1.y, rs, b1.y), 0.f);
        o1.z = fmaxf(fmaf(a1.z, rs, b1.z), 0.f);
        o1.w = fmaxf(fmaf(a1.w, rs, b1.w), 0.f);

        int f0 = lane << 2;            // features [f0, f0+4)
        atomicAdd(&pooled_s[f0 + 0], o0.x);
        atomicAdd(&pooled_s[f0 + 1], o0.y);
        atomicAdd(&pooled_s[f0 + 2], o0.z);
        atomicAdd(&pooled_s[f0 + 3], o0.w);
        int f1 = (lane + 32) << 2;     // features [128+4l, ...)
        atomicAdd(&pooled_s[f1 + 0], o1.x);
        atomicAdd(&pooled_s[f1 + 1], o1.y);
        atomicAdd(&pooled_s[f1 + 2], o1.z);
        atomicAdd(&pooled_s[f1 + 3], o1.w);
    }

    __syncthreads();
    if (threadIdx.x < F) atomicAdd(&g_pooled[threadIdx.x], pooled_s[threadIdx.x]);
}

// ---------------- K5: head  softmax(pooled/N @ W2 + b2) ----------------------
__global__ __launch_bounds__(64) void head_kernel(const float* __restrict__ W2,
                                                  const float* __restrict__ b2,
                                                  float* __restrict__ out, float invN) {
    __shared__ float pooled_s[F];
    __shared__ float sm[C];
    int t = threadIdx.x;
    for (int j = t; j < F; j += C) pooled_s[j] = g_pooled[j] * invN;
    __syncthreads();

    float acc = b2[t];
#pragma unroll 8
    for (int j = 0; j < F; j++) acc = fmaf(pooled_s[j], W2[(size_t)j * C + t], acc);

    sm[t] = acc;
    __syncthreads();
    float m = sm[0];
#pragma unroll
    for (int j = 1; j < C; j++) m = fmaxf(m, sm[j]);
    __syncthreads();
    float e = expf(acc - m);
    sm[t] = e;
    __syncthreads();
    float ssum = 0.f;
#pragma unroll
    for (int j = 0; j < C; j++) ssum += sm[j];
    out[t] = e / ssum;
}

// ---------------- launch ------------------------------------------------------
extern "C" void kernel_launch(void* const* d_in, const int* in_sizes, int n_in,
                              void* d_out, int out_size) {
    const float* x   = (const float*)d_in[0];
    const void*  src = d_in[1];
    const void*  dst = d_in[2];
    const float* W   = (const float*)d_in[3];
    const float* b   = (const float*)d_in[4];
    const float* W2  = (const float*)d_in[5];
    const float* b2  = (const float*)d_in[6];
    float*       out = (float*)d_out;

    const int nodes = in_sizes[0] / F;     // 100000
    const int nE    = in_sizes[1];         // 1600000
    const int nScanBlocks = (nodes + 255) / 256;

    detect_kernel<<<1, 256>>>((const unsigned int*)src);
    zero_kernel<<<256, 256>>>(nodes);
    deg_kernel<<<(nE + 255) / 256, 256>>>(src, dst, nE);

    // CSR build
    scan_a_kernel<<<nScanBlocks, 256>>>(nodes);
    scan_b_kernel<<<1, SCAN_BLOCKS>>>(nScanBlocks);
    scan_c_kernel<<<nScanBlocks, 256>>>(nodes);
    scatter_kernel<<<(nE + 255) / 256, 256>>>(src, dst, nE);

    // GEMM (fused rsqrt(out_deg) row scale)
    dim3 ggrid((nodes + BM - 1) / BM, F / BN);
    gemm_kernel<<<ggrid, 256>>>(x, W, nodes);

    // CSR aggregate + epilogue + pool (warp per node, 8 warps/block)
    int ablocks = (nodes + 7) / 8;
    agg_kernel<<<ablocks, 256>>>(b, nodes);

    head_kernel<<<1, C>>>(W2, b2, out, 1.0f / (float)nodes);
}